// round 1
// baseline (speedup 1.0000x reference)
#include <cuda_runtime.h>

#define FULL 0xffffffffu
constexpr int NQ  = 8;
constexpr int DIM = 256;
constexpr int IND = 512;
constexpr int WPB = 8;           // warps per block
constexpr int TPB = WPB * 32;

// Composite CNOT-ring permutation: state_final[i] = product_state[Q(i)]
__device__ __forceinline__ int qperm(int i) {
    return i ^ (((i >> 1) | (i << 7)) & 255) ^ ((i & 1) << 6);
}
// Bank swizzle for the shared state buffer (rank-4 lane->bank-pair map)
__device__ __forceinline__ int swz(int m) { return m ^ (m >> 3); }

__global__ __launch_bounds__(TPB)
void vqc_kernel(const float* __restrict__ h,
                const float* __restrict__ W,
                const float* __restrict__ bpre,
                const float* __restrict__ wts,
                float* __restrict__ out,
                int B)
{
    __shared__ float4 Wsh[NQ * IND / 4];     // 16 KB
    __shared__ float  Msh[NQ][8];            // Rz*Ry*Rx per qubit (complex 2x2)
    __shared__ float  Bsh[NQ];
    __shared__ float2 Ssh[WPB][DIM];         // 16 KB product-state buffers

    const int tid  = threadIdx.x;
    const int lane = tid & 31;
    const int wrp  = tid >> 5;

    // Stage W_pre into shared (coalesced)
    #pragma unroll
    for (int k = 0; k < (NQ * IND / 4) / TPB; ++k)
        Wsh[tid + k * TPB] = reinterpret_cast<const float4*>(W)[tid + k * TPB];

    // Batch-independent gate matrices M_w = Rz(g)*Ry(b)*Rx(a), once per block
    if (tid < NQ) {
        Bsh[tid] = bpre[tid];
        float al = 0.5f * wts[tid * 3 + 0];
        float be = 0.5f * wts[tid * 3 + 1];
        float ga = 0.5f * wts[tid * 3 + 2];
        float sa, ca, sb, cb, sg, cg;
        sincosf(al, &sa, &ca);
        sincosf(be, &sb, &cb);
        sincosf(ga, &sg, &cg);
        // Ry*Rx
        float r00r =  cb * ca, r00i =  sb * sa;
        float r01r = -sb * ca, r01i = -cb * sa;
        float r10r =  sb * ca, r10i = -cb * sa;
        float r11r =  cb * ca, r11i = -sb * sa;
        // row0 *= e^{-ig/2}, row1 *= e^{+ig/2}
        Msh[tid][0] = r00r * cg + r00i * sg;
        Msh[tid][1] = r00i * cg - r00r * sg;
        Msh[tid][2] = r01r * cg + r01i * sg;
        Msh[tid][3] = r01i * cg - r01r * sg;
        Msh[tid][4] = r10r * cg - r10i * sg;
        Msh[tid][5] = r10i * cg + r10r * sg;
        Msh[tid][6] = r11r * cg - r11i * sg;
        Msh[tid][7] = r11i * cg + r11r * sg;
    }
    __syncthreads();

    for (int b = blockIdx.x * WPB + wrp; b < B; b += gridDim.x * WPB) {
        // ---------- a[8] = h[b] @ W^T (warp-cooperative) ----------
        const float4* hrow = reinterpret_cast<const float4*>(h + (size_t)b * IND);
        float acc[NQ];
        #pragma unroll
        for (int o = 0; o < NQ; ++o) acc[o] = 0.f;
        #pragma unroll
        for (int k = 0; k < IND / 128; ++k) {
            float4 hv = hrow[lane + 32 * k];
            #pragma unroll
            for (int o = 0; o < NQ; ++o) {
                float4 wv = Wsh[o * (IND / 4) + lane + 32 * k];
                acc[o] = fmaf(hv.x, wv.x, fmaf(hv.y, wv.y,
                         fmaf(hv.z, wv.z, fmaf(hv.w, wv.w, acc[o]))));
            }
        }
        #pragma unroll
        for (int o = 0; o < NQ; ++o) {
            #pragma unroll
            for (int off = 16; off; off >>= 1)
                acc[o] += __shfl_xor_sync(FULL, acc[o], off);
        }

        // ---------- per-qubit 2-vector (lanes 0..7) ----------
        float av = acc[0];
        #pragma unroll
        for (int o = 1; o < NQ; ++o) av = (lane == o) ? acc[o] : av;

        float v0r = 0.f, v0i = 0.f, v1r = 0.f, v1i = 0.f;
        if (lane < NQ) {
            float t = tanhf(av + Bsh[lane]) * 1.57079632679489662f;
            t = fminf(fmaxf(t, -3.14159265358979f), 3.14159265358979f);
            float s, c;
            sincosf(0.5f * t, &s, &c);
            const float* m = Msh[lane];
            v0r = m[0] * c + m[2] * s;
            v0i = m[1] * c + m[3] * s;
            v1r = m[4] * c + m[6] * s;
            v1i = m[5] * c + m[7] * s;
        }
        float q0r[NQ], q0i[NQ], q1r[NQ], q1i[NQ];
        #pragma unroll
        for (int w = 0; w < NQ; ++w) {
            q0r[w] = __shfl_sync(FULL, v0r, w);
            q0i[w] = __shfl_sync(FULL, v0i, w);
            q1r[w] = __shfl_sync(FULL, v1r, w);
            q1i[w] = __shfl_sync(FULL, v1i, w);
        }

        // ---------- product state: lane owns indices lane*8+j ----------
        float Ar, Ai;
        {
            int bb = (lane >> 4) & 1;                 // qubit 0 <-> bit7 of i
            Ar = bb ? q1r[0] : q0r[0];
            Ai = bb ? q1i[0] : q0i[0];
        }
        #pragma unroll
        for (int w = 1; w < 5; ++w) {
            int bb = (lane >> (4 - w)) & 1;
            float cr = bb ? q1r[w] : q0r[w];
            float ci = bb ? q1i[w] : q0i[w];
            float nr = Ar * cr - Ai * ci;
            float ni = Ar * ci + Ai * cr;
            Ar = nr; Ai = ni;
        }
        float2* S = Ssh[wrp];
        #pragma unroll
        for (int j = 0; j < 8; ++j) {
            int b5 = (j >> 2) & 1, b6 = (j >> 1) & 1, b7 = j & 1;
            float e6r = b6 ? q1r[6] : q0r[6], e6i = b6 ? q1i[6] : q0i[6];
            float e7r = b7 ? q1r[7] : q0r[7], e7i = b7 ? q1i[7] : q0i[7];
            float tr = e6r * e7r - e6i * e7i;
            float ti = e6r * e7i + e6i * e7r;
            float e5r = b5 ? q1r[5] : q0r[5], e5i = b5 ? q1i[5] : q0i[5];
            float br = e5r * tr - e5i * ti;
            float bi = e5r * ti + e5i * tr;
            float sr0 = Ar * br - Ai * bi;
            float si0 = Ar * bi + Ai * br;
            S[swz(lane * 8 + j)] = make_float2(sr0, si0);
        }
        __syncwarp();

        // ---------- gather CNOT-permuted state ----------
        float sr[8], si[8];
        int Qi[8];
        #pragma unroll
        for (int j = 0; j < 8; ++j) {
            Qi[j] = qperm(lane * 8 + j);
            float2 v = S[swz(Qi[j])];
            sr[j] = v.x; si[j] = v.y;
        }

        // ---------- measurements: X,Y,Z per qubit ----------
        float o24[24];
        float p[8], P = 0.f;
        #pragma unroll
        for (int j = 0; j < 8; ++j) {
            p[j] = sr[j] * sr[j] + si[j] * si[j];
            P += p[j];
        }
        // Q(flip_w) for w=0..4 (partner offsets in product-state index space)
        const int QF[5] = {0xC0, 0x60, 0x30, 0x18, 0x0C};
        #pragma unroll
        for (int w = 0; w < 5; ++w) {          // flip bit lives in the lane index
            int bb = (lane >> (4 - w)) & 1;
            float x = 0.f, y = 0.f;
            if (!bb) {                          // conjugate-pair symmetry: half work
                #pragma unroll
                for (int j = 0; j < 8; ++j) {
                    float2 pv = S[swz(Qi[j] ^ QF[w])];
                    x += sr[j] * pv.x + si[j] * pv.y;   // Re(conj(s)*s')
                    y += sr[j] * pv.y - si[j] * pv.x;   // Im(conj(s)*s'), sign=+1 here
                }
            }
            o24[3 * w]     = 2.f * x;
            o24[3 * w + 1] = 2.f * y;
            o24[3 * w + 2] = bb ? -P : P;
        }
        #pragma unroll
        for (int w = 5; w < 8; ++w) {          // flip bit lives inside the lane's 8
            int jf = 1 << (7 - w);
            float x = 0.f, y = 0.f, z = 0.f;
            #pragma unroll
            for (int j = 0; j < 8; ++j) {
                if ((j & jf) == 0) {
                    int jp = j ^ jf;
                    x += sr[j] * sr[jp] + si[j] * si[jp];
                    y += sr[j] * si[jp] - si[j] * sr[jp];
                    z += p[j] - p[jp];
                }
            }
            o24[3 * w]     = 2.f * x;
            o24[3 * w + 1] = 2.f * y;
            o24[3 * w + 2] = z;
        }

        // ---------- warp reduction of 24 accumulators ----------
        #pragma unroll
        for (int k = 0; k < 24; ++k) {
            #pragma unroll
            for (int off = 16; off; off >>= 1)
                o24[k] += __shfl_xor_sync(FULL, o24[k], off);
        }

        if (lane == 0) {
            float ss = 0.f;
            #pragma unroll
            for (int k = 0; k < 24; ++k) ss += o24[k] * o24[k];
            float inv = 1.f / fmaxf(sqrtf(ss), 1e-12f);
            float4* op = reinterpret_cast<float4*>(out + (size_t)b * 24);
            #pragma unroll
            for (int q = 0; q < 6; ++q)
                op[q] = make_float4(o24[4 * q + 0] * inv, o24[4 * q + 1] * inv,
                                    o24[4 * q + 2] * inv, o24[4 * q + 3] * inv);
        }
        __syncwarp();   // protect shared state buffer before next iteration
    }
}

extern "C" void kernel_launch(void* const* d_in, const int* in_sizes, int n_in,
                              void* d_out, int out_size)
{
    const float* h    = (const float*)d_in[0];
    const float* W    = (const float*)d_in[1];
    const float* bpre = (const float*)d_in[2];
    const float* wts  = (const float*)d_in[3];
    float* out        = (float*)d_out;

    int B = in_sizes[0] / IND;                  // 16384
    int blocks = (B + WPB - 1) / WPB;           // one batch element per warp
    vqc_kernel<<<blocks, TPB>>>(h, W, bpre, wts, out, B);
}

// round 3
// speedup vs baseline: 2.1895x; 2.1895x over previous
#include <cuda_runtime.h>

#define FULL 0xffffffffu
constexpr int NQ  = 8;
constexpr int IND = 512;
constexpr int WPB = 8;           // warps per block
constexpr int TPB = WPB * 32;
constexpr int M4  = 4;           // batch elements per warp pass

__global__ __launch_bounds__(TPB)
void vqc_kernel(const float* __restrict__ h,
                const float* __restrict__ W,
                const float* __restrict__ bpre,
                const float* __restrict__ wts,
                float* __restrict__ out,
                int B)
{
    __shared__ float4 Wsh[NQ * IND / 4];     // 16 KB, W[o][k] as float4
    __shared__ float4 Msh[NQ][2];            // Rz*Ry*Rx per qubit (complex 2x2)
    __shared__ float  Bsh[NQ];

    const int tid  = threadIdx.x;
    const int lane = tid & 31;
    const int wrp  = tid >> 5;

    // Stage W_pre into shared (coalesced)
    #pragma unroll
    for (int k = 0; k < (NQ * IND / 4) / TPB; ++k)
        Wsh[tid + k * TPB] = reinterpret_cast<const float4*>(W)[tid + k * TPB];

    // Batch-independent gate matrices M_w = Rz(g)*Ry(b)*Rx(a), once per block
    if (tid < NQ) {
        Bsh[tid] = bpre[tid];
        float al = 0.5f * wts[tid * 3 + 0];
        float be = 0.5f * wts[tid * 3 + 1];
        float ga = 0.5f * wts[tid * 3 + 2];
        float sa, ca, sb, cb, sg, cg;
        sincosf(al, &sa, &ca);
        sincosf(be, &sb, &cb);
        sincosf(ga, &sg, &cg);
        // Ry*Rx (complex 2x2)
        float r00r =  cb * ca, r00i =  sb * sa;
        float r01r = -sb * ca, r01i = -cb * sa;
        float r10r =  sb * ca, r10i = -cb * sa;
        float r11r =  cb * ca, r11i = -sb * sa;
        // row0 *= e^{-i g/2}, row1 *= e^{+i g/2}
        Msh[tid][0] = make_float4(r00r * cg + r00i * sg,   // m00r
                                  r00i * cg - r00r * sg,   // m00i
                                  r01r * cg + r01i * sg,   // m01r
                                  r01i * cg - r01r * sg);  // m01i
        Msh[tid][1] = make_float4(r10r * cg - r10i * sg,   // m10r
                                  r10i * cg + r10r * sg,   // m10i
                                  r11r * cg - r11i * sg,   // m11r
                                  r11i * cg + r11r * sg);  // m11i
    }
    __syncthreads();

    const int w = lane >> 2;     // qubit owned by this lane after reduction
    const int m = lane & 3;      // element-within-pass owned by this lane

    for (int e0 = (blockIdx.x * WPB + wrp) * M4; e0 < B; e0 += gridDim.x * WPB * M4) {
        // ---------- GEMM: acc[o*4+mm] = <h[e0+mm], W[o]> ----------
        float r[32];
        #pragma unroll
        for (int i = 0; i < 32; ++i) r[i] = 0.f;

        const float4* hr = reinterpret_cast<const float4*>(h) + (size_t)e0 * (IND / 4);
        #pragma unroll
        for (int k = 0; k < 4; ++k) {
            float4 hv[M4];
            #pragma unroll
            for (int mm = 0; mm < M4; ++mm)
                hv[mm] = hr[mm * (IND / 4) + k * 32 + lane];
            #pragma unroll
            for (int o = 0; o < NQ; ++o) {
                float4 wv = Wsh[o * (IND / 4) + k * 32 + lane];
                #pragma unroll
                for (int mm = 0; mm < M4; ++mm) {
                    r[o * 4 + mm] = fmaf(hv[mm].x, wv.x, fmaf(hv[mm].y, wv.y,
                                    fmaf(hv[mm].z, wv.z, fmaf(hv[mm].w, wv.w, r[o * 4 + mm]))));
                }
            }
        }

        // ---------- exchange-tree reduce: lane L ends with full sum of r[L] ----------
        #pragma unroll
        for (int s = 4; s >= 0; --s) {
            const int d = 1 << s;
            const int half = 1 << s;          // n/2 where n = 2<<s
            const bool hi = (lane >> s) & 1;
            #pragma unroll
            for (int j = 0; j < half; ++j) {
                float keep = hi ? r[j + half] : r[j];
                float send = hi ? r[j] : r[j + half];
                keep += __shfl_xor_sync(FULL, send, d);
                r[j] = keep;
            }
        }
        float a = r[0];                       // angle pre-activation for (qubit w, elem m)

        // ---------- single-qubit state & Pauli expectations ----------
        float t = tanhf(a + Bsh[w]) * 1.57079632679489662f;
        t = fminf(fmaxf(t, -3.14159265358979f), 3.14159265358979f);
        float s, c;
        sincosf(0.5f * t, &s, &c);
        float4 m0 = Msh[w][0], m1 = Msh[w][1];
        float v0r = m0.x * c + m0.z * s, v0i = m0.y * c + m0.w * s;
        float v1r = m1.x * c + m1.z * s, v1i = m1.y * c + m1.w * s;
        float x = 2.f * (v0r * v1r + v0i * v1i);
        float y = 2.f * (v0r * v1i - v0i * v1r);
        float z = (v0r * v0r + v0i * v0i) - (v1r * v1r + v1i * v1i);

        // ---------- product scans over the stride-4 lane comb (8 qubits) ----------
        float P = z;                          // inclusive prefix z0..zw
        float G = (w >= 2) ? z : 1.f;         // inclusive prefix of z restricted to w>=2
        #pragma unroll
        for (int d = 1; d < 8; d <<= 1) {
            float tp = __shfl_up_sync(FULL, P, 4 * d);
            float tg = __shfl_up_sync(FULL, G, 4 * d);
            if (w >= d) { P *= tp; G *= tg; }
        }
        float Pexc  = __shfl_up_sync(FULL, P, 4);                      // z0..z_{w-1} (w>=1)
        float xnext = __shfl_sync(FULL, x, m + 4 * ((w + 1) & 7));     // x_{w+1 mod 8}
        float x1    = __shfl_sync(FULL, x, m + 4);
        float y0    = __shfl_sync(FULL, y, m);
        float y1    = __shfl_sync(FULL, y, m + 4);
        float z1    = __shfl_sync(FULL, z, m + 4);
        float G6    = __shfl_sync(FULL, G, m + 24);                    // z2..z6
        float G7    = __shfl_sync(FULL, G, m + 28);                    // z2..z7

        // ---------- assemble the 3 observables this lane owns ----------
        float X = (w == 7) ? (x * xnext * x1) : (x * xnext);
        float Y, Z;
        if (w == 0)      { Y = x * y1 * G7;            Z = z1 * G7; }
        else if (w == 7) { Y = -y0 * y1 * G6 * y;      Z = P; }
        else             { Y = Pexc * y * xnext;       Z = P; }

        // ---------- normalize over the 24 outputs of this element ----------
        float ss = X * X + Y * Y + Z * Z;
        ss += __shfl_xor_sync(FULL, ss, 4);
        ss += __shfl_xor_sync(FULL, ss, 8);
        ss += __shfl_xor_sync(FULL, ss, 16);
        float inv = 1.f / fmaxf(sqrtf(ss), 1e-12f);

        int e = e0 + m;
        if (e < B) {
            float* op = out + (size_t)e * 24 + 3 * w;
            op[0] = X * inv;
            op[1] = Y * inv;
            op[2] = Z * inv;
        }
    }
}

extern "C" void kernel_launch(void* const* d_in, const int* in_sizes, int n_in,
                              void* d_out, int out_size)
{
    const float* h    = (const float*)d_in[0];
    const float* W    = (const float*)d_in[1];
    const float* bpre = (const float*)d_in[2];
    const float* wts  = (const float*)d_in[3];
    float* out        = (float*)d_out;

    int B = in_sizes[0] / IND;                      // 16384
    int blocks = (B + WPB * M4 - 1) / (WPB * M4);   // 512 blocks, one pass per warp
    vqc_kernel<<<blocks, TPB>>>(h, W, bpre, wts, out, B);
}